// round 3
// baseline (speedup 1.0000x reference)
#include <cuda_runtime.h>
#include <cuda_bf16.h>
#include <mma.h>
#include <math.h>

using namespace nvcuda;

// Problem constants
#define SQ    1024         // sequence length
#define HSZ   5120         // hidden size
#define NH    128          // heads
#define DNOPE 128
#define DROPE 64
#define DVV   128
#define RQ    1536
#define RKV   512
#define DQK   192          // DNOPE + DROPE
#define QD    192          // per-head q dim
#define KVD   256          // per-head kv dim (nope 128 + v 128)
#define HCHUNK 16          // heads per scores chunk
#define NCHUNK (NH / HCHUNK)

// ---------------- scratch (static device globals; no allocation allowed) ----
__device__ float g_qc  [SQ * RQ];                      // hidden @ Wq_c
__device__ float g_qcn [SQ * RQ];                      // rmsnorm(g_qc)
__device__ float g_ckvn[SQ * RKV];                     // rmsnorm(ckv[:, :512])
__device__ float g_q   [SQ * NH * QD];                 // q up-proj  [s][h][192] (rope in place)
__device__ float g_kv  [SQ * NH * KVD];                // kv up-proj [s][h][256]
__device__ float g_kr  [SQ * DROPE];                   // roped k_rope (head-shared)
__device__ float g_att [SQ * NH * DVV];                // attention out [s][h*128]
__device__ float g_sc  [(size_t)HCHUNK * SQ * SQ];     // scores chunk (67MB, reused 8x)

// ---------------- generic TF32 wmma GEMM ------------------------------------
// C[M,N] = alpha * A[M,K] @ op(B)
// TB=false: B is [K,N] row-major (NN) ; TB=true: B is [N,K] row-major (NT)
// Dual-source B: for k < K1 read B, for k >= K1 read B2 (e.g. head-shared kr).
// Batched via blockIdx.z with element strides sA/sB/sB2/sC.
#define BM 128
#define BN 64
#define BK 32

template <bool TB> struct BLay { using type = wmma::row_major; };
template <>        struct BLay<true> { using type = wmma::col_major; };

template <bool TB>
__global__ __launch_bounds__(256)
void gemm_tf32(const float* __restrict__ A, const float* __restrict__ B,
               const float* __restrict__ B2, float* __restrict__ C,
               int M, int N, int K, int K1,
               int lda, int ldb, int ldb2, int ldc,
               long long sA, long long sB, long long sB2, long long sC,
               float alpha)
{
    A  += (size_t)blockIdx.z * sA;
    B  += (size_t)blockIdx.z * sB;
    B2 += (size_t)blockIdx.z * sB2;
    C  += (size_t)blockIdx.z * sC;

    __shared__ float As[BM * BK];   // [BM][BK]
    __shared__ float Bs[BK * BN];   // NN: [BK][BN] ; NT: [BN][BK]

    const int m0 = blockIdx.y * BM;
    const int n0 = blockIdx.x * BN;
    const int tid  = threadIdx.x;
    const int warp = tid >> 5;
    const int wm = (warp & 3) * 32;   // warp row offset in tile
    const int wn = (warp >> 2) * 32;  // warp col offset in tile

    wmma::fragment<wmma::accumulator, 16, 16, 8, float> acc[2][2];
    #pragma unroll
    for (int i = 0; i < 2; i++)
        #pragma unroll
        for (int j = 0; j < 2; j++)
            wmma::fill_fragment(acc[i][j], 0.0f);

    for (int k0 = 0; k0 < K; k0 += BK) {
        // load A tile: 128x32 = 4096 floats, 256 threads -> 16 each
        #pragma unroll
        for (int i = 0; i < 16; i++) {
            int idx = tid + i * 256;
            int r = idx >> 5, c = idx & 31;
            As[idx] = wmma::__float_to_tf32(A[(size_t)(m0 + r) * lda + (k0 + c)]);
        }
        // load B tile: 2048 floats -> 8 each
        if (!TB) {
            #pragma unroll
            for (int i = 0; i < 8; i++) {
                int idx = tid + i * 256;
                int r = idx >> 6, c = idx & 63;  // [BK][BN]
                int k = k0 + r;
                float v = (k < K1) ? B [(size_t)k * ldb  + (n0 + c)]
                                   : B2[(size_t)(k - K1) * ldb2 + (n0 + c)];
                Bs[idx] = wmma::__float_to_tf32(v);
            }
        } else {
            #pragma unroll
            for (int i = 0; i < 8; i++) {
                int idx = tid + i * 256;
                int r = idx >> 5, c = idx & 31;  // [BN][BK]
                int k = k0 + c;
                float v = (k < K1) ? B [(size_t)(n0 + r) * ldb  + k]
                                   : B2[(size_t)(n0 + r) * ldb2 + (k - K1)];
                Bs[idx] = wmma::__float_to_tf32(v);
            }
        }
        __syncthreads();

        #pragma unroll
        for (int kk = 0; kk < BK; kk += 8) {
            wmma::fragment<wmma::matrix_a, 16, 16, 8, wmma::precision::tf32, wmma::row_major> af[2];
            wmma::load_matrix_sync(af[0], &As[(wm + 0)  * BK + kk], BK);
            wmma::load_matrix_sync(af[1], &As[(wm + 16) * BK + kk], BK);

            wmma::fragment<wmma::matrix_b, 16, 16, 8, wmma::precision::tf32,
                           typename BLay<TB>::type> bf[2];
            if (!TB) {
                wmma::load_matrix_sync(bf[0], &Bs[kk * BN + wn + 0 ], BN);
                wmma::load_matrix_sync(bf[1], &Bs[kk * BN + wn + 16], BN);
            } else {
                wmma::load_matrix_sync(bf[0], &Bs[(wn + 0 ) * BK + kk], BK);
                wmma::load_matrix_sync(bf[1], &Bs[(wn + 16) * BK + kk], BK);
            }
            #pragma unroll
            for (int i = 0; i < 2; i++)
                #pragma unroll
                for (int j = 0; j < 2; j++)
                    wmma::mma_sync(acc[i][j], af[i], bf[j], acc[i][j]);
        }
        __syncthreads();
    }

    #pragma unroll
    for (int i = 0; i < 2; i++)
        #pragma unroll
        for (int j = 0; j < 2; j++) {
            #pragma unroll
            for (int t = 0; t < acc[i][j].num_elements; t++) acc[i][j].x[t] *= alpha;
            wmma::store_matrix_sync(C + (size_t)(m0 + wm + 16 * i) * ldc + (n0 + wn + 16 * j),
                                    acc[i][j], ldc, wmma::mem_row_major);
        }
}

// ---------------- rmsnorm ---------------------------------------------------
__global__ void rmsnorm_kernel(const float* __restrict__ x, const float* __restrict__ w,
                               float* __restrict__ y, int N, int ldx, int ldy)
{
    x += (size_t)blockIdx.x * ldx;
    y += (size_t)blockIdx.x * ldy;
    __shared__ float sd[256];
    int t = threadIdx.x;
    float s = 0.0f;
    for (int i = t; i < N; i += 256) { float v = x[i]; s += v * v; }
    sd[t] = s; __syncthreads();
    for (int o = 128; o > 0; o >>= 1) { if (t < o) sd[t] += sd[t + o]; __syncthreads(); }
    float r = rsqrtf(sd[0] / (float)N + 1e-6f);
    for (int i = t; i < N; i += 256) y[i] = x[i] * r * w[i];
}

// ---------------- rope -------------------------------------------------------
// Apply rope to the 64-dim rope part of q IN PLACE: thread handles pair (j, j+32).
__global__ void rope_q_kernel(float* __restrict__ q)
{
    int idx = blockIdx.x * blockDim.x + threadIdx.x;    // SQ*NH*32
    if (idx >= SQ * NH * 32) return;
    int j = idx & 31;
    int h = (idx >> 5) & (NH - 1);
    int s = idx >> 12;
    float* base = q + (size_t)s * (NH * QD) + (size_t)h * QD + DNOPE;
    float inv = powf(10000.0f, -(float)j / 32.0f);
    float ang = (float)s * inv;
    float c = cosf(ang), sn = sinf(ang);
    float x1 = base[j], x2 = base[j + 32];
    base[j]      = x1 * c - x2 * sn;
    base[j + 32] = x2 * c + x1 * sn;
}

// rope k_rope (head-shared) from cache[:, 512:576] into g_kr
__global__ void rope_k_kernel(const float* __restrict__ ckv, float* __restrict__ kr)
{
    int idx = blockIdx.x * blockDim.x + threadIdx.x;    // SQ*32
    if (idx >= SQ * 32) return;
    int j = idx & 31;
    int s = idx >> 5;
    const float* base = ckv + (size_t)s * 576 + RKV;
    float inv = powf(10000.0f, -(float)j / 32.0f);
    float ang = (float)s * inv;
    float c = cosf(ang), sn = sinf(ang);
    float x1 = base[j], x2 = base[j + 32];
    kr[(size_t)s * DROPE + j]      = x1 * c - x2 * sn;
    kr[(size_t)s * DROPE + j + 32] = x2 * c + x1 * sn;
}

// ---------------- row softmax ----------------------------------------------
__global__ void softmax_kernel(float* __restrict__ x, int N)
{
    x += (size_t)blockIdx.x * N;
    __shared__ float sd[256];
    int t = threadIdx.x;
    float m = -1e30f;
    for (int i = t; i < N; i += 256) m = fmaxf(m, x[i]);
    sd[t] = m; __syncthreads();
    for (int o = 128; o > 0; o >>= 1) { if (t < o) sd[t] = fmaxf(sd[t], sd[t + o]); __syncthreads(); }
    m = sd[0]; __syncthreads();
    float s = 0.0f;
    for (int i = t; i < N; i += 256) { float e = expf(x[i] - m); x[i] = e; s += e; }
    sd[t] = s; __syncthreads();
    for (int o = 128; o > 0; o >>= 1) { if (t < o) sd[t] += sd[t + o]; __syncthreads(); }
    float inv = 1.0f / sd[0];
    for (int i = t; i < N; i += 256) x[i] *= inv;
}

// ---------------- driver -----------------------------------------------------
extern "C" void kernel_launch(void* const* d_in, const int* in_sizes, int n_in,
                              void* d_out, int out_size)
{
    const float* hidden    = (const float*)d_in[0];   // [1024, 5120]
    const float* Wq_c      = (const float*)d_in[1];   // [5120, 1536]
    const float* q_norm_w  = (const float*)d_in[2];   // [1536]
    const float* Wq_d      = (const float*)d_in[3];   // [1536, 24576]
    const float* Wkv_c     = (const float*)d_in[4];   // [5120, 576]
    const float* kv_norm_w = (const float*)d_in[5];   // [512]
    const float* Wkv_d     = (const float*)d_in[6];   // [512, 32768]
    const float* Wo        = (const float*)d_in[7];   // [16384, 5120]

    float* out   = (float*)d_out;                     // [1024, 5120]
    float* cache = out + (size_t)SQ * HSZ;            // [1024, 576]

    float *p_qc, *p_qcn, *p_ckvn, *p_q, *p_kv, *p_kr, *p_att, *p_sc;
    cudaGetSymbolAddress((void**)&p_qc,  g_qc);
    cudaGetSymbolAddress((void**)&p_qcn, g_qcn);
    cudaGetSymbolAddress((void**)&p_ckvn,g_ckvn);
    cudaGetSymbolAddress((void**)&p_q,   g_q);
    cudaGetSymbolAddress((void**)&p_kv,  g_kv);
    cudaGetSymbolAddress((void**)&p_kr,  g_kr);
    cudaGetSymbolAddress((void**)&p_att, g_att);
    cudaGetSymbolAddress((void**)&p_sc,  g_sc);

    const float scale = 1.0f / sqrtf((float)DQK);

    // 1) q_c = hidden @ Wq_c              [1024,1536]
    gemm_tf32<false><<<dim3(RQ / BN, SQ / BM, 1), 256>>>(
        hidden, Wq_c, Wq_c, p_qc, SQ, RQ, HSZ, HSZ,
        HSZ, RQ, RQ, RQ, 0, 0, 0, 0, 1.0f);

    // 2) ckv = hidden @ Wkv_c -> directly into cache output  [1024,576]
    gemm_tf32<false><<<dim3(576 / BN, SQ / BM, 1), 256>>>(
        hidden, Wkv_c, Wkv_c, cache, SQ, 576, HSZ, HSZ,
        HSZ, 576, 576, 576, 0, 0, 0, 0, 1.0f);

    // 3) rmsnorm
    rmsnorm_kernel<<<SQ, 256>>>(p_qc, q_norm_w, p_qcn, RQ, RQ, RQ);
    rmsnorm_kernel<<<SQ, 256>>>(cache, kv_norm_w, p_ckvn, RKV, 576, RKV);

    // 4) q = qn @ Wq_d                    [1024, 24576]
    gemm_tf32<false><<<dim3((NH * QD) / BN, SQ / BM, 1), 256>>>(
        p_qcn, Wq_d, Wq_d, p_q, SQ, NH * QD, RQ, RQ,
        RQ, NH * QD, NH * QD, NH * QD, 0, 0, 0, 0, 1.0f);

    // 5) kv = ckvn @ Wkv_d                [1024, 32768]
    gemm_tf32<false><<<dim3((NH * KVD) / BN, SQ / BM, 1), 256>>>(
        p_ckvn, Wkv_d, Wkv_d, p_kv, SQ, NH * KVD, RKV, RKV,
        RKV, NH * KVD, NH * KVD, NH * KVD, 0, 0, 0, 0, 1.0f);

    // 6) rope (q in place; k_rope into g_kr)
    rope_q_kernel<<<(SQ * NH * 32 + 255) / 256, 256>>>(p_q);
    rope_k_kernel<<<(SQ * 32 + 255) / 256, 256>>>(cache, p_kr);

    // 7) attention, 16 heads at a time to bound the scores scratch
    for (int ch = 0; ch < NCHUNK; ch++) {
        int h0 = ch * HCHUNK;

        // scores[h] = scale * Q[h] @ [Kn[h] | kr]^T     [16][1024,1024]
        // Q: strided view of g_q (rope already applied), K: dual-source (kv nope + shared kr)
        gemm_tf32<true><<<dim3(SQ / BN, SQ / BM, HCHUNK), 256>>>(
            p_q + (size_t)h0 * QD,                 // A, head stride 192
            p_kv + (size_t)h0 * KVD,               // B  (k < 128): kv nope
            p_kr,                                  // B2 (k >= 128): shared roped kr
            p_sc,
            SQ, SQ, DQK, DNOPE,
            NH * QD, NH * KVD, DROPE, SQ,
            QD, KVD, 0, (long long)SQ * SQ, scale);

        // softmax over rows
        softmax_kernel<<<HCHUNK * SQ, 256>>>(p_sc, SQ);

        // att[:, h*128:(h+1)*128] = probs[h] @ V[h]
        gemm_tf32<false><<<dim3(DVV / BN, SQ / BM, HCHUNK), 256>>>(
            p_sc,
            p_kv + (size_t)h0 * KVD + DNOPE,       // V strided view
            p_kv + (size_t)h0 * KVD + DNOPE,
            p_att + (size_t)h0 * DVV,
            SQ, DVV, SQ, SQ,
            SQ, NH * KVD, NH * KVD, NH * DVV,
            (long long)SQ * SQ, KVD, KVD, DVV, 1.0f);
    }

    // 8) out = att @ Wo                  [1024, 5120]
    gemm_tf32<false><<<dim3(HSZ / BN, SQ / BM, 1), 256>>>(
        p_att, Wo, Wo, out, SQ, HSZ, NH * DVV, NH * DVV,
        NH * DVV, HSZ, HSZ, HSZ, 0, 0, 0, 0, 1.0f);
}

// round 5
// speedup vs baseline: 2.1619x; 2.1619x over previous
#include <cuda_runtime.h>
#include <cuda_bf16.h>
#include <mma.h>
#include <math.h>

using namespace nvcuda;

// Problem constants
#define SQ    1024
#define HSZ   5120
#define NH    128
#define DNOPE 128
#define DROPE 64
#define DVV   128
#define RQ    1536
#define RKV   512
#define DQK   192
#define QD    192
#define KVD   256
#define HCHUNK 16
#define NCHUNK (NH / HCHUNK)

// ---------------- scratch ----------------------------------------------------
__device__ float g_qc  [SQ * RQ];
__device__ float g_qcn [SQ * RQ];
__device__ float g_ckvn[SQ * RKV];
__device__ float g_q   [SQ * NH * QD];                 // rope applied in place
__device__ float g_kv  [SQ * NH * KVD];
__device__ float g_kr  [SQ * DROPE];
__device__ float g_att [SQ * NH * DVV];
__device__ float g_sc  [(size_t)HCHUNK * SQ * SQ];     // 67MB scores chunk

__device__ __forceinline__ float4 cvt4_tf32(float4 v)
{
    float4 w;
    w.x = wmma::__float_to_tf32(v.x);
    w.y = wmma::__float_to_tf32(v.y);
    w.z = wmma::__float_to_tf32(v.z);
    w.w = wmma::__float_to_tf32(v.w);
    return w;
}

// ---------------- pipelined TF32 wmma GEMM ----------------------------------
// C[M,N] = alpha * A[M,K] @ op(B)
// TB=false: B is [K,N] (NN) ; TB=true: B is [N,K] (NT, A@B^T)
// Dual-source B: k < K1 -> B ; k >= K1 -> B2 (K1 must be a multiple of BK).
// GUARD: predicate B loads / C stores on n < N (for N not divisible by BN).
#define BM 128
#define BN 128
#define BK 16

#define LDA_S 20    // BK + 4   (A row-major [m][k])
#define LDBN_S 132  // BN + 4   (B NN row-major [k][n])
#define LDBT_S 20   // BK + 4   (B NT as [n][k], col_major frags)

template <bool TB> struct BLay { using type = wmma::row_major; };
template <>        struct BLay<true> { using type = wmma::col_major; };

template <bool TB, bool GUARD>
__global__ __launch_bounds__(256)
void gemm_tf32(const float* __restrict__ A, const float* __restrict__ B,
               const float* __restrict__ B2, float* __restrict__ C,
               int M, int N, int K, int K1,
               int lda, int ldb, int ldb2, int ldc,
               long long sA, long long sB, long long sB2, long long sC,
               float alpha)
{
    A  += (size_t)blockIdx.z * sA;
    B  += (size_t)blockIdx.z * sB;
    B2 += (size_t)blockIdx.z * sB2;
    C  += (size_t)blockIdx.z * sC;

    __shared__ __align__(16) float As[2][BM * LDA_S];
    __shared__ __align__(16) float Bs[2][BM * LDBT_S > BK * LDBN_S ? BM * LDBT_S : BK * LDBN_S];

    const int m0 = blockIdx.y * BM;
    const int n0 = blockIdx.x * BN;
    const int tid  = threadIdx.x;
    const int warp = tid >> 5;
    const int wm = (warp & 1) * 64;    // 2 warps along M
    const int wn = (warp >> 1) * 32;   // 4 warps along N

    wmma::fragment<wmma::accumulator, 16, 16, 8, float> acc[4][2];
    #pragma unroll
    for (int i = 0; i < 4; i++)
        #pragma unroll
        for (int j = 0; j < 2; j++)
            wmma::fill_fragment(acc[i][j], 0.0f);

    float4 a_pre[2], b_pre[2];

    auto ldg_tile = [&](int t) {
        const int k0 = t * BK;
        #pragma unroll
        for (int i = 0; i < 2; i++) {
            int idx = tid + i * 256;
            {   // A: 128 rows x 16 k -> 512 float4, k-contiguous
                int r = idx >> 2, c = (idx & 3) * 4;
                a_pre[i] = *(const float4*)&A[(size_t)(m0 + r) * lda + (k0 + c)];
            }
            if (!TB) {  // B NN: 16 k x 128 n -> 512 float4, n-contiguous
                int kr = idx >> 5, c = (idx & 31) * 4;
                int gk = k0 + kr;
                int col = n0 + c;
                const float* src = (gk < K1)
                    ? &B [(size_t)gk * ldb + col]
                    : &B2[(size_t)(gk - K1) * ldb2 + col];
                if (GUARD) {
                    float4 v;
                    v.x = (col + 0 < N) ? src[0] : 0.0f;
                    v.y = (col + 1 < N) ? src[1] : 0.0f;
                    v.z = (col + 2 < N) ? src[2] : 0.0f;
                    v.w = (col + 3 < N) ? src[3] : 0.0f;
                    b_pre[i] = v;
                } else {
                    b_pre[i] = *(const float4*)src;
                }
            } else {    // B NT: 128 n x 16 k -> 512 float4, k-contiguous
                int r = idx >> 2, c = (idx & 3) * 4;
                int gk = k0 + c;
                const float* src = (gk < K1)
                    ? &B [(size_t)(n0 + r) * ldb + gk]
                    : &B2[(size_t)(n0 + r) * ldb2 + (gk - K1)];
                b_pre[i] = *(const float4*)src;
            }
        }
    };

    auto sts_tile = [&](int st) {
        #pragma unroll
        for (int i = 0; i < 2; i++) {
            int idx = tid + i * 256;
            {
                int r = idx >> 2, c = (idx & 3) * 4;
                *(float4*)&As[st][r * LDA_S + c] = cvt4_tf32(a_pre[i]);
            }
            if (!TB) {
                int kr = idx >> 5, c = (idx & 31) * 4;
                *(float4*)&Bs[st][kr * LDBN_S + c] = cvt4_tf32(b_pre[i]);
            } else {
                int r = idx >> 2, c = (idx & 3) * 4;
                *(float4*)&Bs[st][r * LDBT_S + c] = cvt4_tf32(b_pre[i]);
            }
        }
    };

    auto compute = [&](int st) {
        #pragma unroll
        for (int kk = 0; kk < BK; kk += 8) {
            wmma::fragment<wmma::matrix_a, 16, 16, 8, wmma::precision::tf32, wmma::row_major> af[4];
            #pragma unroll
            for (int i = 0; i < 4; i++)
                wmma::load_matrix_sync(af[i], &As[st][(wm + 16 * i) * LDA_S + kk], LDA_S);

            wmma::fragment<wmma::matrix_b, 16, 16, 8, wmma::precision::tf32,
                           typename BLay<TB>::type> bf[2];
            #pragma unroll
            for (int j = 0; j < 2; j++) {
                if (!TB)
                    wmma::load_matrix_sync(bf[j], &Bs[st][kk * LDBN_S + wn + 16 * j], LDBN_S);
                else
                    wmma::load_matrix_sync(bf[j], &Bs[st][(wn + 16 * j) * LDBT_S + kk], LDBT_S);
            }
            #pragma unroll
            for (int i = 0; i < 4; i++)
                #pragma unroll
                for (int j = 0; j < 2; j++)
                    wmma::mma_sync(acc[i][j], af[i], bf[j], acc[i][j]);
        }
    };

    const int ntiles = K / BK;

    // prologue: tile 0 -> smem[0]
    ldg_tile(0);
    sts_tile(0);
    __syncthreads();

    for (int t = 0; t < ntiles; ++t) {
        int cur = t & 1;
        bool has_next = (t + 1 < ntiles);
        if (has_next) ldg_tile(t + 1);   // LDGs in flight while we compute
        compute(cur);
        if (has_next) sts_tile(1 - cur);
        __syncthreads();
    }

    // epilogue
    #pragma unroll
    for (int i = 0; i < 4; i++)
        #pragma unroll
        for (int j = 0; j < 2; j++) {
            int cn = n0 + wn + 16 * j;
            if (GUARD && cn + 16 > N) continue;
            #pragma unroll
            for (int t = 0; t < acc[i][j].num_elements; t++) acc[i][j].x[t] *= alpha;
            wmma::store_matrix_sync(C + (size_t)(m0 + wm + 16 * i) * ldc + cn,
                                    acc[i][j], ldc, wmma::mem_row_major);
        }
}

// ---------------- rmsnorm ---------------------------------------------------
__global__ void rmsnorm_kernel(const float* __restrict__ x, const float* __restrict__ w,
                               float* __restrict__ y, int N, int ldx, int ldy)
{
    x += (size_t)blockIdx.x * ldx;
    y += (size_t)blockIdx.x * ldy;
    __shared__ float sd[256];
    int t = threadIdx.x;
    float s = 0.0f;
    for (int i = t; i < N; i += 256) { float v = x[i]; s += v * v; }
    sd[t] = s; __syncthreads();
    for (int o = 128; o > 0; o >>= 1) { if (t < o) sd[t] += sd[t + o]; __syncthreads(); }
    float r = rsqrtf(sd[0] / (float)N + 1e-6f);
    for (int i = t; i < N; i += 256) y[i] = x[i] * r * w[i];
}

// ---------------- rope -------------------------------------------------------
__global__ void rope_q_kernel(float* __restrict__ q)
{
    int idx = blockIdx.x * blockDim.x + threadIdx.x;    // SQ*NH*32
    if (idx >= SQ * NH * 32) return;
    int j = idx & 31;
    int h = (idx >> 5) & (NH - 1);
    int s = idx >> 12;
    float* base = q + (size_t)s * (NH * QD) + (size_t)h * QD + DNOPE;
    float inv = powf(10000.0f, -(float)j / 32.0f);
    float ang = (float)s * inv;
    float c = cosf(ang), sn = sinf(ang);
    float x1 = base[j], x2 = base[j + 32];
    base[j]      = x1 * c - x2 * sn;
    base[j + 32] = x2 * c + x1 * sn;
}

__global__ void rope_k_kernel(const float* __restrict__ ckv, float* __restrict__ kr)
{
    int idx = blockIdx.x * blockDim.x + threadIdx.x;    // SQ*32
    if (idx >= SQ * 32) return;
    int j = idx & 31;
    int s = idx >> 5;
    const float* base = ckv + (size_t)s * 576 + RKV;
    float inv = powf(10000.0f, -(float)j / 32.0f);
    float ang = (float)s * inv;
    float c = cosf(ang), sn = sinf(ang);
    float x1 = base[j], x2 = base[j + 32];
    kr[(size_t)s * DROPE + j]      = x1 * c - x2 * sn;
    kr[(size_t)s * DROPE + j + 32] = x2 * c + x1 * sn;
}

// ---------------- row softmax ----------------------------------------------
__global__ void softmax_kernel(float* __restrict__ x, int N)
{
    x += (size_t)blockIdx.x * N;
    __shared__ float sd[256];
    int t = threadIdx.x;
    float m = -1e30f;
    for (int i = t; i < N; i += 256) m = fmaxf(m, x[i]);
    sd[t] = m; __syncthreads();
    for (int o = 128; o > 0; o >>= 1) { if (t < o) sd[t] = fmaxf(sd[t], sd[t + o]); __syncthreads(); }
    m = sd[0]; __syncthreads();
    float s = 0.0f;
    for (int i = t; i < N; i += 256) { float e = expf(x[i] - m); x[i] = e; s += e; }
    sd[t] = s; __syncthreads();
    for (int o = 128; o > 0; o >>= 1) { if (t < o) sd[t] += sd[t + o]; __syncthreads(); }
    float inv = 1.0f / sd[0];
    for (int i = t; i < N; i += 256) x[i] *= inv;
}

// ---------------- driver -----------------------------------------------------
extern "C" void kernel_launch(void* const* d_in, const int* in_sizes, int n_in,
                              void* d_out, int out_size)
{
    const float* hidden    = (const float*)d_in[0];
    const float* Wq_c      = (const float*)d_in[1];
    const float* q_norm_w  = (const float*)d_in[2];
    const float* Wq_d      = (const float*)d_in[3];
    const float* Wkv_c     = (const float*)d_in[4];
    const float* kv_norm_w = (const float*)d_in[5];
    const float* Wkv_d     = (const float*)d_in[6];
    const float* Wo        = (const float*)d_in[7];

    float* out   = (float*)d_out;                     // [1024, 5120]
    float* cache = out + (size_t)SQ * HSZ;            // [1024, 576]

    float *p_qc, *p_qcn, *p_ckvn, *p_q, *p_kv, *p_kr, *p_att, *p_sc;
    cudaGetSymbolAddress((void**)&p_qc,  g_qc);
    cudaGetSymbolAddress((void**)&p_qcn, g_qcn);
    cudaGetSymbolAddress((void**)&p_ckvn,g_ckvn);
    cudaGetSymbolAddress((void**)&p_q,   g_q);
    cudaGetSymbolAddress((void**)&p_kv,  g_kv);
    cudaGetSymbolAddress((void**)&p_kr,  g_kr);
    cudaGetSymbolAddress((void**)&p_att, g_att);
    cudaGetSymbolAddress((void**)&p_sc,  g_sc);

    const float scale = 1.0f / sqrtf((float)DQK);

    // 1) q_c = hidden @ Wq_c              [1024,1536]
    gemm_tf32<false,false><<<dim3(RQ / BN, SQ / BM, 1), 256>>>(
        hidden, Wq_c, Wq_c, p_qc, SQ, RQ, HSZ, HSZ,
        HSZ, RQ, RQ, RQ, 0, 0, 0, 0, 1.0f);

    // 2) ckv = hidden @ Wkv_c -> cache    [1024,576]  (N=576 needs guard)
    gemm_tf32<false,true><<<dim3((576 + BN - 1) / BN, SQ / BM, 1), 256>>>(
        hidden, Wkv_c, Wkv_c, cache, SQ, 576, HSZ, HSZ,
        HSZ, 576, 576, 576, 0, 0, 0, 0, 1.0f);

    // 3) rmsnorm
    rmsnorm_kernel<<<SQ, 256>>>(p_qc, q_norm_w, p_qcn, RQ, RQ, RQ);
    rmsnorm_kernel<<<SQ, 256>>>(cache, kv_norm_w, p_ckvn, RKV, 576, RKV);

    // 4) q = qn @ Wq_d                    [1024, 24576]
    gemm_tf32<false,false><<<dim3((NH * QD) / BN, SQ / BM, 1), 256>>>(
        p_qcn, Wq_d, Wq_d, p_q, SQ, NH * QD, RQ, RQ,
        RQ, NH * QD, NH * QD, NH * QD, 0, 0, 0, 0, 1.0f);

    // 5) kv = ckvn @ Wkv_d                [1024, 32768]
    gemm_tf32<false,false><<<dim3((NH * KVD) / BN, SQ / BM, 1), 256>>>(
        p_ckvn, Wkv_d, Wkv_d, p_kv, SQ, NH * KVD, RKV, RKV,
        RKV, NH * KVD, NH * KVD, NH * KVD, 0, 0, 0, 0, 1.0f);

    // 6) rope (q in place; shared k_rope)
    rope_q_kernel<<<(SQ * NH * 32 + 255) / 256, 256>>>(p_q);
    rope_k_kernel<<<(SQ * 32 + 255) / 256, 256>>>(cache, p_kr);

    // 7) attention, 16 heads per chunk
    for (int ch = 0; ch < NCHUNK; ch++) {
        int h0 = ch * HCHUNK;

        // scores = scale * Q @ [Kn | kr]^T   (NT dual-source, K1=128)
        gemm_tf32<true,false><<<dim3(SQ / BN, SQ / BM, HCHUNK), 256>>>(
            p_q + (size_t)h0 * QD,
            p_kv + (size_t)h0 * KVD,
            p_kr,
            p_sc,
            SQ, SQ, DQK, DNOPE,
            NH * QD, NH * KVD, DROPE, SQ,
            QD, KVD, 0, (long long)SQ * SQ, scale);

        softmax_kernel<<<HCHUNK * SQ, 256>>>(p_sc, SQ);

        // att = probs @ V
        gemm_tf32<false,false><<<dim3(DVV / BN, SQ / BM, HCHUNK), 256>>>(
            p_sc,
            p_kv + (size_t)h0 * KVD + DNOPE,
            p_kv + (size_t)h0 * KVD + DNOPE,
            p_att + (size_t)h0 * DVV,
            SQ, DVV, SQ, SQ,
            SQ, NH * KVD, NH * KVD, NH * DVV,
            (long long)SQ * SQ, KVD, KVD, DVV, 1.0f);
    }

    // 8) out = att @ Wo                   [1024, 5120]
    gemm_tf32<false,false><<<dim3(HSZ / BN, SQ / BM, 1), 256>>>(
        p_att, Wo, Wo, out, SQ, HSZ, NH * DVV, NH * DVV,
        NH * DVV, HSZ, HSZ, HSZ, 0, 0, 0, 0, 1.0f);
}